// round 7
// baseline (speedup 1.0000x reference)
#include <cuda_runtime.h>
#include <cuda_fp16.h>

#define NN 100000
#define EE 1200000
#define HID 64
#define NG 256
#define OC 10
#define IN0 7

// ---- scratch (static device globals) ----
__device__ int   g_cnti[NN];
__device__ int   g_rowp[NN];
__device__ int   g_cursor[NN];
__device__ int   g_total;
__device__ uint2 g_edge[EE];              // packed {src, wgt-bits}
__device__ float g_dis[NN];
__device__ __align__(32) float g_xp[NN * 8];   // x padded to 8ch
__device__ float g_aggx[NN * 8];               // layer-0 aggregate (8ch padded)
__device__ __align__(256) __half g_hwh[NN * HID];
__device__ float g_agg[NN * HID];
__device__ float g_sums[NG * HID];
__device__ float g_gcnt[NG];

// ---- zero counters + pad x to 8 channels ----
__global__ void k_zero(const float* __restrict__ x) {
    int i = blockIdx.x * blockDim.x + threadIdx.x;
    if (i < NN) {
        g_cnti[i] = 0;
        float4 a, b;
        const float* xr = x + (long long)i * IN0;
        a.x = xr[0]; a.y = xr[1]; a.z = xr[2]; a.w = xr[3];
        b.x = xr[4]; b.y = xr[5]; b.z = xr[6]; b.w = 0.0f;
        ((float4*)(g_xp + (long long)i * 8))[0] = a;
        ((float4*)(g_xp + (long long)i * 8))[1] = b;
    }
    if (i < NG * HID) g_sums[i] = 0.0f;
    if (i < NG) g_gcnt[i] = 0.0f;
    if (i == 0) g_total = 0;
}

// ---- histogram on dst ----
__global__ void k_hist(const int* __restrict__ ei) {
    int e = blockIdx.x * blockDim.x + threadIdx.x;
    if (e < EE) atomicAdd(&g_cnti[ei[EE + e]], 1);
}

// ---- fused scan: per-block local scan + atomic base claim ----
__global__ void k_scanA() {
    __shared__ int sm[256];
    __shared__ int base_sm;
    int t = threadIdx.x;
    int i = blockIdx.x * 256 + t;
    int v = (i < NN) ? g_cnti[i] : 0;
    sm[t] = v;
    __syncthreads();
#pragma unroll
    for (int off = 1; off < 256; off <<= 1) {
        int add = (t >= off) ? sm[t - off] : 0;
        __syncthreads();
        sm[t] += add;
        __syncthreads();
    }
    if (t == 255) base_sm = atomicAdd(&g_total, sm[255]);
    __syncthreads();
    if (i < NN) {
        int r = base_sm + sm[t] - v;
        g_rowp[i] = r;
        g_cursor[i] = r;
        g_dis[i] = rsqrtf((float)v + 1.0f);
    }
}

// ---- fill CSR (packed records) ----
__global__ void k_fill(const int* __restrict__ ei) {
    int e = blockIdx.x * blockDim.x + threadIdx.x;
    if (e >= EE) return;
    int src = ei[e];
    int dst = ei[EE + e];
    int pos = atomicAdd(&g_cursor[dst], 1);
    float w = g_dis[src] * g_dis[dst];
    g_edge[pos] = make_uint2((unsigned)src, __float_as_uint(w));
}

// ---- layer-0 gather over padded x: 8 threads/node ----
__global__ void k_gather7() {
    int t = threadIdx.x;
    int n = blockIdx.x * 32 + (t >> 3);
    int c = t & 7;
    if (n >= NN) return;
    int s0 = g_rowp[n], deg = g_cnti[n];
    float d = g_dis[n];
    float acc0 = d * d * g_xp[(long long)n * 8 + c];
    float acc1 = 0.0f;
    int e = s0, end = s0 + deg;
    for (; e + 1 < end; e += 2) {
        uint2 ea = g_edge[e], eb = g_edge[e + 1];
        acc0 += __uint_as_float(ea.y) * g_xp[(long long)ea.x * 8 + c];
        acc1 += __uint_as_float(eb.y) * g_xp[(long long)eb.x * 8 + c];
    }
    if (e < end) {
        uint2 ea = g_edge[e];
        acc0 += __uint_as_float(ea.y) * g_xp[(long long)ea.x * 8 + c];
    }
    g_aggx[(long long)n * 8 + c] = acc0 + acc1;
}

// ---- dense mm7: agg = aggx @ W0 + b0 (aggx stride 8, use 7) ----
__global__ void k_mm7(const float* __restrict__ W,
                      const float* __restrict__ b) {
    __shared__ float4 Ws[IN0 * 16];
    __shared__ float  hs[16 * 8];
    __shared__ float4 bs[16];
    int t = threadIdx.x;
    if (t < IN0 * 16) Ws[t] = ((const float4*)W)[t];
    if (t < 16) bs[t] = ((const float4*)b)[t];
    int node0 = blockIdx.x * 16;
    if (t < 128) {
        int nd = node0 + (t >> 3);
        hs[t] = (nd < NN) ? g_aggx[(long long)nd * 8 + (t & 7)] : 0.0f;
    }
    __syncthreads();
    int node = node0 + (t >> 4);
    int q = t & 15;
    if (node < NN) {
        const float* hrow = &hs[(t >> 4) * 8];
        float4 s = bs[q];
#pragma unroll
        for (int k = 0; k < IN0; k++) {
            float hv = hrow[k];
            float4 w = Ws[k * 16 + q];
            s.x += hv * w.x; s.y += hv * w.y; s.z += hv * w.z; s.w += hv * w.w;
        }
        ((float4*)&g_agg[(long long)node * HID])[q] = s;
    }
}

// ---- dense mm64: hwh = fp16( relu(agg) @ W ), 64 nodes/block ----
__global__ void k_mm64(const float* __restrict__ W) {
    __shared__ float4 Ws4[HID * 16];    // 16 KB, loaded once per 64 nodes
    __shared__ float4 hs4[16 * 16];     // 4 KB
    int t = threadIdx.x;
#pragma unroll
    for (int i = 0; i < 4; i++) Ws4[t + 256 * i] = ((const float4*)W)[t + 256 * i];
    int nl = t >> 4;
    int q = t & 15;
#pragma unroll
    for (int g = 0; g < 4; g++) {
        int node = blockIdx.x * 64 + g * 16 + nl;
        __syncthreads();                 // covers Ws4 (g=0) and hs4 reuse
        float4 v = make_float4(0.f, 0.f, 0.f, 0.f);
        if (node < NN) v = ((const float4*)&g_agg[(long long)node * HID])[q];
        v.x = fmaxf(v.x, 0.f); v.y = fmaxf(v.y, 0.f);
        v.z = fmaxf(v.z, 0.f); v.w = fmaxf(v.w, 0.f);
        hs4[nl * 16 + q] = v;
        __syncthreads();
        if (node < NN) {
            const float* hrow = (const float*)&hs4[nl * 16];
            float4 s = make_float4(0.f, 0.f, 0.f, 0.f);
#pragma unroll
            for (int k = 0; k < HID; k++) {
                float hv = hrow[k];
                float4 w = Ws4[k * 16 + q];
                s.x += hv * w.x; s.y += hv * w.y; s.z += hv * w.z; s.w += hv * w.w;
            }
            __half2 h0 = __floats2half2_rn(s.x, s.y);
            __half2 h1 = __floats2half2_rn(s.z, s.w);
            uint2 o;
            o.x = *(unsigned int*)&h0;
            o.y = *(unsigned int*)&h1;
            ((uint2*)(g_hwh + (long long)node * HID))[q] = o;
        }
    }
}

// ---- fp16 row unpack helper ----
__device__ __forceinline__ void unpack8(uint4 u, float* f) {
    const __half2* h = (const __half2*)&u;
#pragma unroll
    for (int j = 0; j < 4; j++) {
        float2 p = __half22float2(h[j]);
        f[2 * j] = p.x;
        f[2 * j + 1] = p.y;
    }
}

__device__ __forceinline__ void fma8(float* acc, float w, const float* f) {
#pragma unroll
    for (int i = 0; i < 8; i++) acc[i] += w * f[i];
}

// ---- 64-ch gather over fp16 hw: 8 threads/node, 4-edge unroll ----
__global__ void k_gather64h(const float* __restrict__ b) {
    int t = threadIdx.x;
    int n = blockIdx.x * 32 + (t >> 3);
    int q = t & 7;                       // channels [8q, 8q+8)
    if (n >= NN) return;
    int s0 = g_rowp[n], deg = g_cnti[n];
    float d = g_dis[n];
    float dd = d * d;
    float acc[8], acc2[8], tmp[8];
    uint4 self = ((const uint4*)(g_hwh + (long long)n * HID))[q];
    unpack8(self, tmp);
    float4 b0 = ((const float4*)b)[q * 2];
    float4 b1 = ((const float4*)b)[q * 2 + 1];
    acc[0] = dd * tmp[0] + b0.x; acc[1] = dd * tmp[1] + b0.y;
    acc[2] = dd * tmp[2] + b0.z; acc[3] = dd * tmp[3] + b0.w;
    acc[4] = dd * tmp[4] + b1.x; acc[5] = dd * tmp[5] + b1.y;
    acc[6] = dd * tmp[6] + b1.z; acc[7] = dd * tmp[7] + b1.w;
#pragma unroll
    for (int i = 0; i < 8; i++) acc2[i] = 0.0f;
    int e = s0, end = s0 + deg;
    for (; e + 3 < end; e += 4) {
        uint2 e0 = g_edge[e],     e1 = g_edge[e + 1];
        uint2 e2 = g_edge[e + 2], e3 = g_edge[e + 3];
        uint4 v0 = ((const uint4*)(g_hwh + (long long)e0.x * HID))[q];
        uint4 v1 = ((const uint4*)(g_hwh + (long long)e1.x * HID))[q];
        uint4 v2 = ((const uint4*)(g_hwh + (long long)e2.x * HID))[q];
        uint4 v3 = ((const uint4*)(g_hwh + (long long)e3.x * HID))[q];
        float f0[8], f1[8], f2[8], f3[8];
        unpack8(v0, f0); unpack8(v1, f1); unpack8(v2, f2); unpack8(v3, f3);
        fma8(acc,  __uint_as_float(e0.y), f0);
        fma8(acc2, __uint_as_float(e1.y), f1);
        fma8(acc,  __uint_as_float(e2.y), f2);
        fma8(acc2, __uint_as_float(e3.y), f3);
    }
    for (; e < end; e++) {
        uint2 e0 = g_edge[e];
        uint4 v0 = ((const uint4*)(g_hwh + (long long)e0.x * HID))[q];
        float f0[8];
        unpack8(v0, f0);
        fma8(acc, __uint_as_float(e0.y), f0);
    }
#pragma unroll
    for (int i = 0; i < 8; i++) acc[i] += acc2[i];
    float4* ap = (float4*)&g_agg[(long long)n * HID + q * 8];
    ap[0] = make_float4(acc[0], acc[1], acc[2], acc[3]);
    ap[1] = make_float4(acc[4], acc[5], acc[6], acc[7]);
}

// ---- global mean pool: batch sorted ----
#define NPB 256
__global__ void k_pool(const int* __restrict__ batch) {
    int c = threadIdx.x;          // 0..63
    int n0 = blockIdx.x * NPB;
    int n1 = min(n0 + NPB, NN);
    int cur_g = batch[n0];
    float acc = 0.0f, cnt = 0.0f;
    for (int n = n0; n < n1; n++) {
        int g = batch[n];
        if (g != cur_g) {
            atomicAdd(&g_sums[cur_g * HID + c], acc);
            if (c == 0) atomicAdd(&g_gcnt[cur_g], cnt);
            acc = 0.0f; cnt = 0.0f; cur_g = g;
        }
        acc += g_agg[(long long)n * HID + c];
        cnt += 1.0f;
    }
    atomicAdd(&g_sums[cur_g * HID + c], acc);
    if (c == 0) atomicAdd(&g_gcnt[cur_g], cnt);
}

// ---- final linear ----
__global__ void k_fin(const float* __restrict__ lw,
                      const float* __restrict__ lb,
                      float* __restrict__ out) {
    int g = threadIdx.x;
    if (g >= NG) return;
    float inv = 1.0f / fmaxf(g_gcnt[g], 1.0f);
    float acc[OC];
#pragma unroll
    for (int o = 0; o < OC; o++) acc[o] = lb[o];
    for (int k = 0; k < HID; k++) {
        float v = g_sums[g * HID + k] * inv;
#pragma unroll
        for (int o = 0; o < OC; o++) acc[o] += v * lw[k * OC + o];
    }
#pragma unroll
    for (int o = 0; o < OC; o++) out[g * OC + o] = acc[o];
}

extern "C" void kernel_launch(void* const* d_in, const int* in_sizes, int n_in,
                              void* d_out, int out_size) {
    const float* x   = (const float*)d_in[0];
    const int* ei    = (const int*)d_in[1];
    const int* bat   = (const int*)d_in[2];
    const float* W0  = (const float*)d_in[3];
    const float* b0  = (const float*)d_in[4];
    const float* W1  = (const float*)d_in[5];
    const float* b1  = (const float*)d_in[6];
    const float* W2  = (const float*)d_in[7];
    const float* b2  = (const float*)d_in[8];
    const float* lw  = (const float*)d_in[9];
    const float* lb  = (const float*)d_in[10];
    float* out       = (float*)d_out;

    const int TB = 256;
    // CSR build
    k_zero<<<(NN + TB - 1) / TB, TB>>>(x);
    k_hist<<<(EE + TB - 1) / TB, TB>>>(ei);
    k_scanA<<<(NN + 255) / 256, 256>>>();
    k_fill<<<(EE + TB - 1) / TB, TB>>>(ei);

    int g32_grid = (NN + 31) / 32;

    // layer 0
    k_gather7<<<g32_grid, TB>>>();
    k_mm7<<<(NN + 15) / 16, TB>>>(W0, b0);

    // layer 1
    k_mm64<<<(NN + 63) / 64, TB>>>(W1);
    k_gather64h<<<g32_grid, TB>>>(b1);

    // layer 2
    k_mm64<<<(NN + 63) / 64, TB>>>(W2);
    k_gather64h<<<g32_grid, TB>>>(b2);

    // pool + linear
    k_pool<<<(NN + NPB - 1) / NPB, 64>>>(bat);
    k_fin<<<1, TB>>>(lw, lb, out);
}